// round 4
// baseline (speedup 1.0000x reference)
#include <cuda_runtime.h>

#define H    128
#define FF   8
#define C4   512
#define MB   16     // batch rows per CTA (2048 = 128 CTAs x 16, exact)
#define NT   256
#define NP   8      // f32x2 row-pairs per thread (16 rows)

// U re-blocked for coalesced loads: UB[((k>>2)*C4 + c)*4 + (k&3)].
// Thread handling column c loads float4 = U[4b..4b+3][c]; adjacent lanes
// (adjacent c) read adjacent 16B -> warp LDG.128 covers 4 lines only.
__device__ __align__(16) float g_UBe[C4 * H];
__device__ __align__(16) float g_UBd[C4 * H];

typedef unsigned long long u64;

__device__ __forceinline__ u64 dup2(float v) {
    u64 r; asm("mov.b64 %0, {%1, %1};" : "=l"(r) : "f"(v)); return r;
}
__device__ __forceinline__ void fma2(u64& d, u64 a, u64 b) {
    asm("fma.rn.f32x2 %0, %1, %2, %0;" : "+l"(d) : "l"(a), "l"(b));
}
__device__ __forceinline__ void unpack2(u64 v, float& lo, float& hi) {
    asm("mov.b64 {%0, %1}, %2;" : "=f"(lo), "=f"(hi) : "l"(v));
}
__device__ __forceinline__ float ex2f(float x){ float r; asm("ex2.approx.f32 %0, %1;" : "=f"(r) : "f"(x)); return r; }
__device__ __forceinline__ float rcpf(float x){ float r; asm("rcp.approx.f32 %0, %1;" : "=f"(r) : "f"(x)); return r; }
__device__ __forceinline__ float sigm(float x){ return rcpf(1.f + ex2f(-1.4426950408889634f * x)); }
__device__ __forceinline__ float tanhf_(float x){ return fmaf(-2.f, rcpf(1.f + ex2f(2.8853900817779268f * x)), 1.f); }

__global__ void transposeU_kernel(const float* __restrict__ Ue, const float* __restrict__ Ud) {
    int i = blockIdx.x * blockDim.x + threadIdx.x;
    if (i < H * C4) {
        int k = i / C4, c = i % C4;
        int idx = (((k >> 2) * C4) + c) * 4 + (k & 3);
        g_UBe[idx] = Ue[i];
        g_UBd[idx] = Ud[i];
    }
}

// Persistent batch-parallel LSTM autoencoder. One CTA owns 16 batch rows for
// all 1024 steps. Thread t owns gate columns (t, t+256); batch rows live in
// the f32x2 lanes (8 pairs). h read as LDS.128 broadcasts; U read coalesced.
__global__ void __launch_bounds__(NT, 1)
lstm_ae_kernel(const float* __restrict__ x,
               const float* __restrict__ We, const float* __restrict__ be,
               const float* __restrict__ Wd, const float* __restrict__ bd,
               const float* __restrict__ Wo, const float* __restrict__ bog,
               float* __restrict__ out, int T)
{
    __shared__ __align__(16) float hsm[H][MB];    // h[j][m]; stores & pair-reads conflict-free
    __shared__ __align__(16) float zsm[C4][MB];   // z[c][(m+c)&15] swizzle
    __shared__ __align__(16) float xsm[FF][MB];   // step input, [f][m]
    __shared__ float wosm[H * FF];

    const int tid = threadIdx.x;
    const int rs  = blockIdx.x * MB;

    for (int i = tid; i < H * MB; i += NT) (&hsm[0][0])[i] = 0.f;
    for (int i = tid; i < H * FF; i += NT) wosm[i] = Wo[i];

    const int c0 = tid, c1 = tid + NT;

    float cst[NP];
    #pragma unroll
    for (int p = 0; p < NP; p++) cst[p] = 0.f;

    const int  xm = tid >> 3, xf = tid & 7;
    const bool xth = tid < MB * FF;
    const float bof = bog[xf];

    if (xth) xsm[xf][xm] = x[(size_t)(rs + xm) * T * FF + xf];   // t = 0
    __syncthreads();

    for (int phase = 0; phase < 2; phase++) {
        const bool dec = (phase == 1);
        const float4* U4 = (const float4*)(dec ? g_UBd : g_UBe);
        const float*  Wm = dec ? Wd : We;
        const float*  bv = dec ? bd : be;

        u64 wd0[FF], wd1[FF];
        #pragma unroll
        for (int f = 0; f < FF; f++) {
            wd0[f] = dup2(Wm[f * C4 + c0]);
            wd1[f] = dup2(Wm[f * C4 + c1]);
        }
        const u64 bb0 = dup2(bv[c0]);
        const u64 bb1 = dup2(bv[c1]);

        for (int t = 0; t < T; t++) {
            // ---- z = b + x@W + h@U ----
            u64 a0[NP], a1[NP];
            #pragma unroll
            for (int p = 0; p < NP; p++) { a0[p] = bb0; a1[p] = bb1; }

            #pragma unroll
            for (int f = 0; f < FF; f++) {
                #pragma unroll
                for (int q = 0; q < 4; q++) {
                    ulonglong2 xp = *(const ulonglong2*)&xsm[f][4 * q];  // LDS.128 bcast
                    fma2(a0[2*q    ], xp.x, wd0[f]);
                    fma2(a0[2*q + 1], xp.y, wd0[f]);
                    fma2(a1[2*q    ], xp.x, wd1[f]);
                    fma2(a1[2*q + 1], xp.y, wd1[f]);
                }
            }

            float4 u0 = U4[c0];
            float4 u1 = U4[c1];
            #pragma unroll 2
            for (int blk = 0; blk < 31; blk++) {
                float4 n0 = U4[(size_t)(blk + 1) * C4 + c0];   // coalesced LDG.128
                float4 n1 = U4[(size_t)(blk + 1) * C4 + c1];
                #pragma unroll
                for (int kk = 0; kk < 4; kk++) {
                    const int k = blk * 4 + kk;
                    u64 d0 = dup2(((const float*)&u0)[kk]);
                    u64 d1 = dup2(((const float*)&u1)[kk]);
                    #pragma unroll
                    for (int q = 0; q < 4; q++) {
                        ulonglong2 hp = *(const ulonglong2*)&hsm[k][4 * q];  // LDS.128 bcast
                        fma2(a0[2*q    ], hp.x, d0);
                        fma2(a0[2*q + 1], hp.y, d0);
                        fma2(a1[2*q    ], hp.x, d1);
                        fma2(a1[2*q + 1], hp.y, d1);
                    }
                }
                u0 = n0; u1 = n1;
            }
            #pragma unroll
            for (int kk = 0; kk < 4; kk++) {                    // blk = 31 tail
                const int k = 124 + kk;
                u64 d0 = dup2(((const float*)&u0)[kk]);
                u64 d1 = dup2(((const float*)&u1)[kk]);
                #pragma unroll
                for (int q = 0; q < 4; q++) {
                    ulonglong2 hp = *(const ulonglong2*)&hsm[k][4 * q];
                    fma2(a0[2*q    ], hp.x, d0);
                    fma2(a0[2*q + 1], hp.y, d0);
                    fma2(a1[2*q    ], hp.x, d1);
                    fma2(a1[2*q + 1], hp.y, d1);
                }
            }

            // swizzled z exchange: slot(m, c) = (m + c) & 15 -> conflict-free R/W
            #pragma unroll
            for (int p = 0; p < NP; p++) {
                float l0, h0v; unpack2(a0[p], l0, h0v);
                float l1, h1v; unpack2(a1[p], l1, h1v);
                int s0 = (2 * p + c0) & 15;
                zsm[c0][s0] = l0; zsm[c0][(s0 + 1) & 15] = h0v;
                int s1 = (2 * p + c1) & 15;
                zsm[c1][s1] = l1; zsm[c1][(s1 + 1) & 15] = h1v;
            }
            __syncthreads();

            // ---- gates + state update; e -> (m = e&15, j = e>>4) keeps all
            //      z-reads and h-writes conflict-free ----
            #pragma unroll
            for (int i = 0; i < NP; i++) {
                int e = tid + NT * i;
                int m = e & 15, j = e >> 4;
                int sl = (m + j) & 15;                 // 128 == 0 mod 16
                float zi = zsm[j      ][sl];
                float zf = zsm[j + 128][sl];
                float zg = zsm[j + 256][sl];
                float zo = zsm[j + 384][sl];
                float ig = sigm(zi), fg = sigm(zf);
                float gg = tanhf_(zg), og = sigm(zo);
                float c  = fmaf(fg, cst[i], ig * gg);
                cst[i] = c;
                hsm[j][m] = og * tanhf_(c);
            }

            if (!dec) {
                if (xth && t + 1 < T)   // after t=T-1 xsm keeps x[:,T-1,:] = decoder y0
                    xsm[xf][xm] = x[(size_t)(rs + xm) * T * FF + (size_t)(t + 1) * FF + xf];
                __syncthreads();
            } else {
                __syncthreads();
                // ---- y = relu(h @ W_out + b_out); feed back + emit ----
                if (xth) {
                    float a = 0.f, b2 = 0.f, c2 = 0.f, d2 = 0.f;
                    #pragma unroll 8
                    for (int k = 0; k < H; k += 4) {
                        a  = fmaf(hsm[k    ][xm], wosm[(k    ) * FF + xf], a);
                        b2 = fmaf(hsm[k + 1][xm], wosm[(k + 1) * FF + xf], b2);
                        c2 = fmaf(hsm[k + 2][xm], wosm[(k + 2) * FF + xf], c2);
                        d2 = fmaf(hsm[k + 3][xm], wosm[(k + 3) * FF + xf], d2);
                    }
                    float y = fmaxf(bof + ((a + b2) + (c2 + d2)), 0.f);
                    xsm[xf][xm] = y;
                    out[(size_t)(rs + xm) * T * FF + (size_t)t * FF + xf] = y;
                }
                __syncthreads();
            }
        }
    }
}

extern "C" void kernel_launch(void* const* d_in, const int* in_sizes, int n_in,
                              void* d_out, int out_size)
{
    const float* x  = (const float*)d_in[0];
    const float* We = (const float*)d_in[1];
    const float* Ue = (const float*)d_in[2];
    const float* be = (const float*)d_in[3];
    const float* Wd = (const float*)d_in[4];
    const float* Ud = (const float*)d_in[5];
    const float* bd = (const float*)d_in[6];
    const float* Wo = (const float*)d_in[7];
    const float* bo = (const float*)d_in[8];
    float* out = (float*)d_out;

    const int B = 2048;
    const int T = in_sizes[0] / (B * FF);

    transposeU_kernel<<<(H * C4 + 255) / 256, 256>>>(Ue, Ud);
    lstm_ae_kernel<<<B / MB, NT>>>(x, We, be, Wd, bd, Wo, bo, out, T);
}

// round 5
// speedup vs baseline: 1.0216x; 1.0216x over previous
#include <cuda_runtime.h>

#define H   128
#define FF  8
#define C4  512
#define MB  14      // batch rows per CTA
#define NT  128
#define NP  7       // f32x2 row-pairs per thread
#define BB  2048

// U re-blocked as UG[k][j][gate]: thread j loads float4 = U[k][{j,128+j,256+j,384+j}]
// in one 16B read; adjacent lanes (adjacent j) are contiguous -> coalesced LDG.128.
__device__ __align__(16) float g_UGe[H * C4];
__device__ __align__(16) float g_UGd[H * C4];

typedef unsigned long long u64;

__device__ __forceinline__ u64 dup2(float v) {
    u64 r; asm("mov.b64 %0, {%1, %1};" : "=l"(r) : "f"(v)); return r;
}
__device__ __forceinline__ u64 pack2(float lo, float hi) {
    u64 r; asm("mov.b64 %0, {%1, %2};" : "=l"(r) : "f"(lo), "f"(hi)); return r;
}
__device__ __forceinline__ void fma2(u64& d, u64 a, u64 b) {
    asm("fma.rn.f32x2 %0, %1, %2, %0;" : "+l"(d) : "l"(a), "l"(b));
}
__device__ __forceinline__ void unpack2(u64 v, float& lo, float& hi) {
    asm("mov.b64 {%0, %1}, %2;" : "=f"(lo), "=f"(hi) : "l"(v));
}
__device__ __forceinline__ float ex2f(float x){ float r; asm("ex2.approx.f32 %0, %1;" : "=f"(r) : "f"(x)); return r; }
__device__ __forceinline__ float rcpf(float x){ float r; asm("rcp.approx.f32 %0, %1;" : "=f"(r) : "f"(x)); return r; }
__device__ __forceinline__ float sigm(float x){ return rcpf(1.f + ex2f(-1.4426950408889634f * x)); }
__device__ __forceinline__ float tanhf_(float x){ return fmaf(-2.f, rcpf(1.f + ex2f(2.8853900817779268f * x)), 1.f); }

// load 7 row-pairs (14 rows) from a 16-float row: 3x LDS.128 + 1x LDS.64
__device__ __forceinline__ void load_pairs(u64* hp, const float* row) {
    ulonglong2 a = *(const ulonglong2*)(row);
    ulonglong2 b = *(const ulonglong2*)(row + 4);
    ulonglong2 c = *(const ulonglong2*)(row + 8);
    u64        d = *(const u64*)(row + 12);
    hp[0] = a.x; hp[1] = a.y; hp[2] = b.x; hp[3] = b.y;
    hp[4] = c.x; hp[5] = c.y; hp[6] = d;
}

__global__ void transposeU_kernel(const float* __restrict__ Ue, const float* __restrict__ Ud) {
    int i = blockIdx.x * blockDim.x + threadIdx.x;
    if (i < H * C4) {
        int k = i / C4, c = i % C4;
        int o = (k * H + (c & 127)) * 4 + (c >> 7);
        g_UGe[o] = Ue[i];
        g_UGd[o] = Ud[i];
    }
}

// Persistent LSTM autoencoder. CTA owns 14 batch rows for all 1024 steps.
// Thread j = tid owns the 4 gate columns of h-unit j; the 14 batch rows live
// in f32x2 lanes (7 pairs). Gate math happens in registers (no z exchange).
__global__ void __launch_bounds__(NT, 1)
lstm_ae_kernel(const float* __restrict__ x,
               const float* __restrict__ We, const float* __restrict__ be,
               const float* __restrict__ Wd, const float* __restrict__ bd,
               const float* __restrict__ Wo, const float* __restrict__ bog,
               float* __restrict__ out, int T)
{
    __shared__ __align__(16) float hsm[H][16];   // h[j][m]
    __shared__ __align__(16) float xsm[FF][16];  // step input / decoder feedback [f][m]
    __shared__ __align__(16) float wsm[FF * C4]; // W blocked [f][j][g]
    __shared__ float wosm[H * FF];

    const int tid = threadIdx.x;
    const int j   = tid;
    const int rs  = blockIdx.x * MB;

    for (int i = tid; i < H * 16; i += NT) (&hsm[0][0])[i] = 0.f;
    for (int i = tid; i < FF * 16; i += NT) (&xsm[0][0])[i] = 0.f;
    for (int i = tid; i < H * FF; i += NT) wosm[i] = Wo[i];

    float cst[MB];
    #pragma unroll
    for (int m = 0; m < MB; m++) cst[m] = 0.f;

    const int  xm = tid >> 3, xf = tid & 7;
    const bool xth = tid < MB * FF;
    const bool gx  = xth && (rs + xm < BB);
    const float bof = bog[xf];
    const float* xrow = x + (size_t)(rs + xm) * T * FF + xf;   // valid only if gx
    float*       orow = out + (size_t)(rs + xm) * T * FF + xf;

    if (gx) xsm[xf][xm] = xrow[0];   // t = 0
    __syncthreads();

    for (int phase = 0; phase < 2; phase++) {
        const bool dec = (phase == 1);
        const float4* UG4 = (const float4*)(dec ? g_UGd : g_UGe) + j;
        const float*  Wm  = dec ? Wd : We;
        const float*  bv  = dec ? bd : be;

        // stage W into smem, blocked [f][j][g]
        for (int i = tid; i < FF * C4; i += NT) {
            int f = i >> 9, c = i & 511;
            wsm[(f * H + (c & 127)) * 4 + (c >> 7)] = Wm[i];
        }
        u64 bdv[4];
        #pragma unroll
        for (int g = 0; g < 4; g++) bdv[g] = dup2(bv[g * H + j]);
        __syncthreads();

        for (int t = 0; t < T; t++) {
            // ---- z = b + x@W + h@U (all 4 gates of unit j, 7 row-pairs) ----
            u64 acc[4][NP];
            #pragma unroll
            for (int g = 0; g < 4; g++)
                #pragma unroll
                for (int p = 0; p < NP; p++) acc[g][p] = bdv[g];

            #pragma unroll
            for (int f = 0; f < FF; f++) {
                u64 xp[NP];
                load_pairs(xp, &xsm[f][0]);
                float4 wf4 = *(const float4*)&wsm[(f * H + j) * 4];
                #pragma unroll
                for (int g = 0; g < 4; g++) {
                    u64 wd = dup2(((const float*)&wf4)[g]);
                    #pragma unroll
                    for (int p = 0; p < NP; p++) fma2(acc[g][p], xp[p], wd);
                }
            }

            for (int kb = 0; kb < H; kb += 2) {
                // batch loads ahead of the fma block (ILP for 1 warp/SMSP)
                float4 u0 = UG4[(kb    ) << 7];
                float4 u1 = UG4[(kb + 1) << 7];
                u64 ha[NP], hb[NP];
                load_pairs(ha, &hsm[kb    ][0]);
                load_pairs(hb, &hsm[kb + 1][0]);
                #pragma unroll
                for (int g = 0; g < 4; g++) {
                    u64 d0 = dup2(((const float*)&u0)[g]);
                    #pragma unroll
                    for (int p = 0; p < NP; p++) fma2(acc[g][p], ha[p], d0);
                }
                #pragma unroll
                for (int g = 0; g < 4; g++) {
                    u64 d1 = dup2(((const float*)&u1)[g]);
                    #pragma unroll
                    for (int p = 0; p < NP; p++) fma2(acc[g][p], hb[p], d1);
                }
            }
            __syncthreads();   // all GEMM reads of hsm/xsm done

            // ---- gates in registers; write h pairs for unit j ----
            u64* hrow = (u64*)&hsm[j][0];
            #pragma unroll
            for (int p = 0; p < NP; p++) {
                float zi0, zi1, zf0, zf1, zg0, zg1, zo0, zo1;
                unpack2(acc[0][p], zi0, zi1);
                unpack2(acc[1][p], zf0, zf1);
                unpack2(acc[2][p], zg0, zg1);
                unpack2(acc[3][p], zo0, zo1);
                float c0 = fmaf(sigm(zf0), cst[2*p    ], sigm(zi0) * tanhf_(zg0));
                float c1 = fmaf(sigm(zf1), cst[2*p + 1], sigm(zi1) * tanhf_(zg1));
                cst[2*p    ] = c0;
                cst[2*p + 1] = c1;
                float h0 = sigm(zo0) * tanhf_(c0);
                float h1 = sigm(zo1) * tanhf_(c1);
                hrow[p] = pack2(h0, h1);
            }

            if (!dec) {
                if (gx && t + 1 < T)    // after t=T-1, xsm keeps x[:,T-1,:] = decoder y0
                    xsm[xf][xm] = xrow[(size_t)(t + 1) * FF];
                __syncthreads();
            } else {
                __syncthreads();        // h complete
                if (xth) {
                    float a = 0.f, b2 = 0.f, c2 = 0.f, d2 = 0.f;
                    #pragma unroll 8
                    for (int k = 0; k < H; k += 4) {
                        a  = fmaf(hsm[k    ][xm], wosm[(k    ) * FF + xf], a);
                        b2 = fmaf(hsm[k + 1][xm], wosm[(k + 1) * FF + xf], b2);
                        c2 = fmaf(hsm[k + 2][xm], wosm[(k + 2) * FF + xf], c2);
                        d2 = fmaf(hsm[k + 3][xm], wosm[(k + 3) * FF + xf], d2);
                    }
                    float y = fmaxf(bof + ((a + b2) + (c2 + d2)), 0.f);
                    xsm[xf][xm] = y;
                    if (gx) orow[(size_t)t * FF] = y;
                }
                __syncthreads();        // y feedback visible before next GEMM
            }
        }
    }
}

extern "C" void kernel_launch(void* const* d_in, const int* in_sizes, int n_in,
                              void* d_out, int out_size)
{
    const float* x  = (const float*)d_in[0];
    const float* We = (const float*)d_in[1];
    const float* Ue = (const float*)d_in[2];
    const float* be = (const float*)d_in[3];
    const float* Wd = (const float*)d_in[4];
    const float* Ud = (const float*)d_in[5];
    const float* bd = (const float*)d_in[6];
    const float* Wo = (const float*)d_in[7];
    const float* bo = (const float*)d_in[8];
    float* out = (float*)d_out;

    const int T = in_sizes[0] / (BB * FF);

    transposeU_kernel<<<(H * C4 + 255) / 256, 256>>>(Ue, Ud);
    lstm_ae_kernel<<<(BB + MB - 1) / MB, NT>>>(x, We, be, Wd, bd, Wo, bo, out, T);
}

// round 6
// speedup vs baseline: 1.0375x; 1.0156x over previous
#include <cuda_runtime.h>

#define H   128
#define FF  8
#define C4  512
#define MB  14      // batch rows per CTA
#define NT  256
#define BB  2048

// U re-blocked as UG[k][j][gate]: thread j loads float4 = U[k][{j,128+j,256+j,384+j}]
// in one 16B read; adjacent lanes contiguous -> coalesced LDG.128, L1-resident.
__device__ __align__(16) float g_UGe[H * C4];
__device__ __align__(16) float g_UGd[H * C4];

typedef unsigned long long u64;

__device__ __forceinline__ u64 dup2(float v) {
    u64 r; asm("mov.b64 %0, {%1, %1};" : "=l"(r) : "f"(v)); return r;
}
__device__ __forceinline__ u64 pack2(float lo, float hi) {
    u64 r; asm("mov.b64 %0, {%1, %2};" : "=l"(r) : "f"(lo), "f"(hi)); return r;
}
__device__ __forceinline__ void fma2(u64& d, u64 a, u64 b) {
    asm("fma.rn.f32x2 %0, %1, %2, %0;" : "+l"(d) : "l"(a), "l"(b));
}
__device__ __forceinline__ void unpack2(u64 v, float& lo, float& hi) {
    asm("mov.b64 {%0, %1}, %2;" : "=f"(lo), "=f"(hi) : "l"(v));
}
__device__ __forceinline__ float ex2f(float x){ float r; asm("ex2.approx.f32 %0, %1;" : "=f"(r) : "f"(x)); return r; }
__device__ __forceinline__ float rcpf(float x){ float r; asm("rcp.approx.f32 %0, %1;" : "=f"(r) : "f"(x)); return r; }
__device__ __forceinline__ float sigm(float x){ return rcpf(1.f + ex2f(-1.4426950408889634f * x)); }
__device__ __forceinline__ float tanhf_(float x){ return fmaf(-2.f, rcpf(1.f + ex2f(2.8853900817779268f * x)), 1.f); }

// bar.sync 0 arrived by all warps (from divergent-but-balanced paths)
#define BARSYNC() asm volatile("bar.sync 0;" ::: "memory")

// Load NPm row-pairs starting at float offset PB (row pointer pre-offset).
template<int NPm>
__device__ __forceinline__ void load_pairsN(u64* hp, const float* row) {
    ulonglong2 a = *(const ulonglong2*)(row);          // LDS.128
    hp[0] = a.x; hp[1] = a.y;
    if (NPm == 4) {
        ulonglong2 b = *(const ulonglong2*)(row + 4);  // LDS.128
        hp[2] = b.x; hp[3] = b.y;
    } else {
        hp[2] = *(const u64*)(row + 4);                // LDS.64
    }
}

__global__ void transposeU_kernel(const float* __restrict__ Ue, const float* __restrict__ Ud) {
    int i = blockIdx.x * blockDim.x + threadIdx.x;
    if (i < H * C4) {
        int k = i / C4, c = i % C4;
        int o = (k * H + (c & 127)) * 4 + (c >> 7);
        g_UGe[o] = Ue[i];
        g_UGd[o] = Ud[i];
    }
}

// Core body, templated on this thread-half's pair count (4 or 3) and the
// starting float offset PB within a 16-float row (0 or 8).
template<int NPm, int PB>
__device__ __forceinline__ void lstm_body(
    int tid, int rs, int T,
    const float* __restrict__ x,
    const float* __restrict__ We, const float* __restrict__ be,
    const float* __restrict__ Wd, const float* __restrict__ bd,
    const float* __restrict__ bog,
    float* __restrict__ out,
    float (&hsm)[2][H][16], float (&xsm)[2][FF][16],
    float* wsm, const float* wosm)
{
    const int j = tid & (H - 1);
    const int xm = tid >> 3, xf = tid & 7;
    const bool xth = tid < MB * FF;                 // only lower half qualifies
    const bool gx  = xth && (rs + xm < BB);
    const float bof = bog[xf];
    const float* xrow = x   + (size_t)(rs + xm) * T * FF + xf;
    float*       orow = out + (size_t)(rs + xm) * T * FF + xf;

    float cst[2 * NPm];
    #pragma unroll
    for (int i = 0; i < 2 * NPm; i++) cst[i] = 0.f;

    int buf = 0;

    for (int phase = 0; phase < 2; phase++) {
        const bool dec = (phase == 1);
        const float4* UG4 = (const float4*)(dec ? g_UGd : g_UGe) + j;
        const float*  Wm  = dec ? Wd : We;
        const float*  bv  = dec ? bd : be;

        // stage W into smem blocked [f][j][g] (cooperative; identical in both halves)
        for (int i = tid; i < FF * C4; i += NT) {
            int f = i >> 9, c = i & 511;
            wsm[(f * H + (c & 127)) * 4 + (c >> 7)] = Wm[i];
        }
        u64 bdv[4];
        #pragma unroll
        for (int g = 0; g < 4; g++) bdv[g] = dup2(bv[g * H + j]);
        BARSYNC();

        for (int t = 0; t < T; t++) {
            const int nbuf = buf ^ 1;

            // ---- z = b + x@W + h@U : 4 gates x NPm row-pairs in registers ----
            u64 acc[4][NPm];
            #pragma unroll
            for (int g = 0; g < 4; g++)
                #pragma unroll
                for (int p = 0; p < NPm; p++) acc[g][p] = bdv[g];

            #pragma unroll
            for (int f = 0; f < FF; f++) {
                u64 xp[NPm];
                load_pairsN<NPm>(xp, &xsm[buf][f][PB]);
                float4 wf4 = ((const float4*)wsm)[f * H + j];
                #pragma unroll
                for (int g = 0; g < 4; g++) {
                    u64 wd = dup2(((const float*)&wf4)[g]);
                    #pragma unroll
                    for (int p = 0; p < NPm; p++) fma2(acc[g][p], xp[p], wd);
                }
            }

            for (int kb = 0; kb < H; kb += 2) {
                float4 u0 = UG4[(kb    ) << 7];     // coalesced LDG.128 (L1-hot)
                float4 u1 = UG4[(kb + 1) << 7];
                u64 ha[NPm], hb[NPm];
                load_pairsN<NPm>(ha, &hsm[buf][kb    ][PB]);
                load_pairsN<NPm>(hb, &hsm[buf][kb + 1][PB]);
                #pragma unroll
                for (int g = 0; g < 4; g++) {
                    u64 d0 = dup2(((const float*)&u0)[g]);
                    #pragma unroll
                    for (int p = 0; p < NPm; p++) fma2(acc[g][p], ha[p], d0);
                }
                #pragma unroll
                for (int g = 0; g < 4; g++) {
                    u64 d1 = dup2(((const float*)&u1)[g]);
                    #pragma unroll
                    for (int p = 0; p < NPm; p++) fma2(acc[g][p], hb[p], d1);
                }
            }

            // ---- gates in registers; write h pairs into the OTHER buffer ----
            u64* hrow = (u64*)&hsm[nbuf][j][PB];
            #pragma unroll
            for (int p = 0; p < NPm; p++) {
                float zi0, zi1, zf0, zf1, zg0, zg1, zo0, zo1;
                unpack2(acc[0][p], zi0, zi1);
                unpack2(acc[1][p], zf0, zf1);
                unpack2(acc[2][p], zg0, zg1);
                unpack2(acc[3][p], zo0, zo1);
                float c0 = fmaf(sigm(zf0), cst[2*p    ], sigm(zi0) * tanhf_(zg0));
                float c1 = fmaf(sigm(zf1), cst[2*p + 1], sigm(zi1) * tanhf_(zg1));
                cst[2*p    ] = c0;
                cst[2*p + 1] = c1;
                hrow[p] = pack2(sigm(zo0) * tanhf_(c0), sigm(zo1) * tanhf_(c1));
            }

            if (!dec) {
                // prefetch next input into the other x buffer (no WAR hazard);
                // clamp at T-1 so the decoder's first read sees x[:,T-1,:].
                if (gx) {
                    int tn = (t + 1 < T) ? (t + 1) : (T - 1);
                    xsm[nbuf][xf][xm] = xrow[(size_t)tn * FF];
                }
                BARSYNC();                           // 1 barrier / encoder step
            } else {
                BARSYNC();                           // h(nbuf) complete
                if (xth) {
                    float a = 0.f, b2 = 0.f, c2 = 0.f, d2 = 0.f;
                    #pragma unroll 8
                    for (int k = 0; k < H; k += 4) {
                        a  = fmaf(hsm[nbuf][k    ][xm], wosm[(k    ) * FF + xf], a);
                        b2 = fmaf(hsm[nbuf][k + 1][xm], wosm[(k + 1) * FF + xf], b2);
                        c2 = fmaf(hsm[nbuf][k + 2][xm], wosm[(k + 2) * FF + xf], c2);
                        d2 = fmaf(hsm[nbuf][k + 3][xm], wosm[(k + 3) * FF + xf], d2);
                    }
                    float y = fmaxf(bof + ((a + b2) + (c2 + d2)), 0.f);
                    xsm[nbuf][xf][xm] = y;
                    if (gx) orow[(size_t)t * FF] = y;
                }
                BARSYNC();                           // y feedback visible
            }
            buf = nbuf;
        }
    }
}

__global__ void __launch_bounds__(NT, 1)
lstm_ae_kernel(const float* __restrict__ x,
               const float* __restrict__ We, const float* __restrict__ be,
               const float* __restrict__ Wd, const float* __restrict__ bd,
               const float* __restrict__ Wo, const float* __restrict__ bog,
               float* __restrict__ out, int T)
{
    __shared__ __align__(16) float hsm[2][H][16];
    __shared__ __align__(16) float xsm[2][FF][16];
    __shared__ __align__(16) float wsm[FF * C4];
    __shared__ float wosm[H * FF];

    const int tid = threadIdx.x;
    const int rs  = blockIdx.x * MB;

    for (int i = tid; i < 2 * H * 16; i += NT) (&hsm[0][0][0])[i] = 0.f;
    for (int i = tid; i < 2 * FF * 16; i += NT) (&xsm[0][0][0])[i] = 0.f;
    for (int i = tid; i < H * FF; i += NT) wosm[i] = Wo[i];

    {   // t = 0 input
        const int xm = tid >> 3, xf = tid & 7;
        if (tid < MB * FF && rs + xm < BB)
            xsm[0][xf][xm] = x[(size_t)(rs + xm) * T * FF + xf];
    }
    __syncthreads();

    if (tid < 128)
        lstm_body<4, 0>(tid, rs, T, x, We, be, Wd, bd, bog, out, hsm, xsm, wsm, wosm);
    else
        lstm_body<3, 8>(tid, rs, T, x, We, be, Wd, bd, bog, out, hsm, xsm, wsm, wosm);
}

extern "C" void kernel_launch(void* const* d_in, const int* in_sizes, int n_in,
                              void* d_out, int out_size)
{
    const float* x  = (const float*)d_in[0];
    const float* We = (const float*)d_in[1];
    const float* Ue = (const float*)d_in[2];
    const float* be = (const float*)d_in[3];
    const float* Wd = (const float*)d_in[4];
    const float* Ud = (const float*)d_in[5];
    const float* bd = (const float*)d_in[6];
    const float* Wo = (const float*)d_in[7];
    const float* bo = (const float*)d_in[8];
    float* out = (float*)d_out;

    const int T = in_sizes[0] / (BB * FF);

    transposeU_kernel<<<(H * C4 + 255) / 256, 256>>>(Ue, Ud);
    lstm_ae_kernel<<<(BB + MB - 1) / MB, NT>>>(x, We, be, Wd, bd, Wo, bo, out, T);
}

// round 7
// speedup vs baseline: 1.3128x; 1.2654x over previous
#include <cuda_runtime.h>

#define H   128
#define FF  8
#define C4  512
#define MB  14     // batch rows per CTA
#define NT  256
#define BB  2048
#define KH  64     // k-range per group

// U blocked as UG[k][j][gate] (float4 per (k,j)): coalesced LDG.128.
__device__ __align__(16) float g_UGe[H * C4];
__device__ __align__(16) float g_UGd[H * C4];

typedef unsigned long long u64;

__device__ __forceinline__ u64 dup2(float v) {
    u64 r; asm("mov.b64 %0, {%1, %1};" : "=l"(r) : "f"(v)); return r;
}
__device__ __forceinline__ u64 pack2(float lo, float hi) {
    u64 r; asm("mov.b64 %0, {%1, %2};" : "=l"(r) : "f"(lo), "f"(hi)); return r;
}
__device__ __forceinline__ void fma2(u64& d, u64 a, u64 b) {
    asm("fma.rn.f32x2 %0, %1, %2, %0;" : "+l"(d) : "l"(a), "l"(b));
}
__device__ __forceinline__ void add2(u64& d, u64 a) {
    asm("add.rn.f32x2 %0, %0, %1;" : "+l"(d) : "l"(a));
}
__device__ __forceinline__ void unpack2(u64 v, float& lo, float& hi) {
    asm("mov.b64 {%0, %1}, %2;" : "=f"(lo), "=f"(hi) : "l"(v));
}
__device__ __forceinline__ float ex2f(float x){ float r; asm("ex2.approx.f32 %0, %1;" : "=f"(r) : "f"(x)); return r; }
__device__ __forceinline__ float rcpf(float x){ float r; asm("rcp.approx.f32 %0, %1;" : "=f"(r) : "f"(x)); return r; }
__device__ __forceinline__ float sigm(float x){ return rcpf(1.f + ex2f(-1.4426950408889634f * x)); }
__device__ __forceinline__ float tanhf_(float x){ return fmaf(-2.f, rcpf(1.f + ex2f(2.8853900817779268f * x)), 1.f); }

#define BARSYNC() asm volatile("bar.sync 0;" ::: "memory")

// 7 row-pairs (14 rows) from a 16-float row: 3x LDS.128 + 1x LDS.64, broadcast
__device__ __forceinline__ void load_pairs7(u64* hp, const float* row) {
    ulonglong2 a = *(const ulonglong2*)(row);
    ulonglong2 b = *(const ulonglong2*)(row + 4);
    ulonglong2 c = *(const ulonglong2*)(row + 8);
    hp[0] = a.x; hp[1] = a.y; hp[2] = b.x; hp[3] = b.y;
    hp[4] = c.x; hp[5] = c.y;
    hp[6] = *(const u64*)(row + 12);
}

__global__ void transposeU_kernel(const float* __restrict__ Ue, const float* __restrict__ Ud) {
    int i = blockIdx.x * blockDim.x + threadIdx.x;
    if (i < H * C4) {
        int k = i / C4, c = i % C4;
        int o = (k * H + (c & 127)) * 4 + (c >> 7);
        g_UGe[o] = Ue[i];
        g_UGd[o] = Ud[i];
    }
}

// dyn smem layout (floats): hsm[2][128][16] | xsm[2][8][16] | wsm[4096] | wosm[1024] | zex(u64 x 3584)
#define SM_H   0
#define SM_X   4096
#define SM_W   4352
#define SM_WO  8448
#define SM_ZX  9472
#define SM_FLOATS (SM_ZX + 7168)

// Group G covers k in [G*64, G*64+64); G0 additionally handles the x-GEMM,
// bias, input prefetch and decoder head. Gate math: G0 keeps pairs 0-3,
// G1 keeps pairs 4-6; the complement partials cross via zex once per step.
template<int G>
__device__ __forceinline__ void lstm_body(
    int tid, int rs, int T,
    const float* __restrict__ x,
    const float* __restrict__ We, const float* __restrict__ be,
    const float* __restrict__ Wd, const float* __restrict__ bd,
    const float* __restrict__ bog,
    float* __restrict__ out,
    float* hsm, float* xsm, float* wsm, const float* wosm, u64* zex)
{
    constexpr int P0  = G ? 4 : 0;   // kept pairs
    constexpr int NPk = G ? 3 : 4;
    constexpr int W0  = G ? 0 : 4;   // written (crossing) pairs
    constexpr int NPw = G ? 4 : 3;
    const int kk0 = G * KH;
    const int j   = tid & (H - 1);

    const int  xm = tid >> 3, xf = tid & 7;
    const bool xth = tid < MB * FF;             // subset of G0 only
    const bool gx  = xth && (rs + xm < BB);
    const float bof = bog[xf];
    const float* xrow = x   + (size_t)(rs + xm) * T * FF + xf;
    float*       orow = out + (size_t)(rs + xm) * T * FF + xf;

    float cst[2 * NPk];
    #pragma unroll
    for (int i = 0; i < 2 * NPk; i++) cst[i] = 0.f;

    int buf = 0;

    for (int phase = 0; phase < 2; phase++) {
        const bool dec = (phase == 1);
        const float4* UG4 = ((const float4*)(dec ? g_UGd : g_UGe)) + j;
        const float*  Wm  = dec ? Wd : We;
        const float*  bv  = dec ? bd : be;

        for (int i = tid; i < FF * C4; i += NT) {      // stage W [f][j][g]
            int f = i >> 9, c = i & 511;
            wsm[(f * H + (c & 127)) * 4 + (c >> 7)] = Wm[i];
        }
        u64 bdv[4];
        if (G == 0) {
            #pragma unroll
            for (int g = 0; g < 4; g++) bdv[g] = dup2(bv[g * H + j]);
        }
        BARSYNC();

        for (int t = 0; t < T; t++) {
            const int nbuf = buf ^ 1;
            const float* hbuf = hsm + buf  * 2048;
            float*       hnew = hsm + nbuf * 2048;
            const float* xbuf = xsm + buf  * 128;

            u64 acc[4][7];
            #pragma unroll
            for (int g = 0; g < 4; g++)
                #pragma unroll
                for (int p = 0; p < 7; p++) acc[g][p] = (G == 0) ? bdv[g] : 0ull;

            if (G == 0) {                               // x @ W
                #pragma unroll
                for (int f = 0; f < FF; f++) {
                    u64 xp[7];
                    load_pairs7(xp, xbuf + f * 16);
                    float4 wf4 = ((const float4*)wsm)[f * H + j];
                    #pragma unroll
                    for (int g = 0; g < 4; g++) {
                        u64 wd = dup2(((const float*)&wf4)[g]);
                        #pragma unroll
                        for (int p = 0; p < 7; p++) fma2(acc[g][p], xp[p], wd);
                    }
                }
            }

            // h @ U over this group's k-half; U prefetched one 4-k block ahead
            float4 uc[4], un[4];
            #pragma unroll
            for (int q = 0; q < 4; q++) uc[q] = UG4[(kk0 + q) << 7];
            for (int kb = 0; kb < KH; kb += 4) {
                const int kn = (kb + 4 < KH) ? kb + 4 : 0;   // wrap: harmless reload
                #pragma unroll
                for (int q = 0; q < 4; q++) un[q] = UG4[(kk0 + kn + q) << 7];
                #pragma unroll
                for (int q = 0; q < 4; q++) {
                    u64 hp[7];
                    load_pairs7(hp, hbuf + (kk0 + kb + q) * 16);
                    #pragma unroll
                    for (int g = 0; g < 4; g++) {
                        u64 d = dup2(((const float*)&uc[q])[g]);
                        #pragma unroll
                        for (int p = 0; p < 7; p++) fma2(acc[g][p], hp[p], d);
                    }
                }
                #pragma unroll
                for (int q = 0; q < 4; q++) uc[q] = un[q];
            }

            // cross partials for non-kept pairs
            #pragma unroll
            for (int g = 0; g < 4; g++)
                #pragma unroll
                for (int pi = 0; pi < NPw; pi++) {
                    const int p = W0 + pi;
                    zex[(g * 7 + p) * H + j] = acc[g][p];
                }
            BARSYNC();

            // gather + gates for kept pairs; write h into the other buffer
            u64* hrow = (u64*)(hnew + j * 16);
            #pragma unroll
            for (int pi = 0; pi < NPk; pi++) {
                const int p = P0 + pi;
                #pragma unroll
                for (int g = 0; g < 4; g++) add2(acc[g][p], zex[(g * 7 + p) * H + j]);
                float zi0, zi1, zf0, zf1, zg0, zg1, zo0, zo1;
                unpack2(acc[0][p], zi0, zi1);
                unpack2(acc[1][p], zf0, zf1);
                unpack2(acc[2][p], zg0, zg1);
                unpack2(acc[3][p], zo0, zo1);
                float c0 = fmaf(sigm(zf0), cst[2*pi    ], sigm(zi0) * tanhf_(zg0));
                float c1 = fmaf(sigm(zf1), cst[2*pi + 1], sigm(zi1) * tanhf_(zg1));
                cst[2*pi    ] = c0;
                cst[2*pi + 1] = c1;
                hrow[p] = pack2(sigm(zo0) * tanhf_(c0), sigm(zo1) * tanhf_(c1));
            }

            if (!dec) {
                if (G == 0 && gx) {        // prefetch next x; clamp keeps x[:,T-1,:]
                    int tn = (t + 1 < T) ? (t + 1) : (T - 1);
                    (xsm + nbuf * 128)[xf * 16 + xm] = xrow[(size_t)tn * FF];
                }
                BARSYNC();                 // h(nbuf) + x(nbuf) ready
            } else {
                BARSYNC();                 // h(nbuf) complete
                if (xth) {
                    float a = 0.f, b2 = 0.f, c2 = 0.f, d2 = 0.f;
                    #pragma unroll 8
                    for (int k = 0; k < H; k += 4) {
                        a  = fmaf(hnew[(k    ) * 16 + xm], wosm[(k    ) * FF + xf], a);
                        b2 = fmaf(hnew[(k + 1) * 16 + xm], wosm[(k + 1) * FF + xf], b2);
                        c2 = fmaf(hnew[(k + 2) * 16 + xm], wosm[(k + 2) * FF + xf], c2);
                        d2 = fmaf(hnew[(k + 3) * 16 + xm], wosm[(k + 3) * FF + xf], d2);
                    }
                    float y = fmaxf(bof + ((a + b2) + (c2 + d2)), 0.f);
                    (xsm + nbuf * 128)[xf * 16 + xm] = y;
                    if (gx) orow[(size_t)t * FF] = y;
                }
                BARSYNC();                 // y feedback visible
            }
            buf = nbuf;
        }
    }
}

__global__ void __launch_bounds__(NT, 1)
lstm_ae_kernel(const float* __restrict__ x,
               const float* __restrict__ We, const float* __restrict__ be,
               const float* __restrict__ Wd, const float* __restrict__ bd,
               const float* __restrict__ Wo, const float* __restrict__ bog,
               float* __restrict__ out, int T)
{
    extern __shared__ __align__(16) float sm[];
    float* hsm  = sm + SM_H;
    float* xsm  = sm + SM_X;
    float* wsm  = sm + SM_W;
    float* wosm = sm + SM_WO;
    u64*   zex  = (u64*)(sm + SM_ZX);

    const int tid = threadIdx.x;
    const int rs  = blockIdx.x * MB;

    for (int i = tid; i < SM_W; i += NT) sm[i] = 0.f;       // hsm + xsm
    for (int i = tid; i < H * FF; i += NT) wosm[i] = Wo[i];
    {
        const int xm = tid >> 3, xf = tid & 7;
        if (tid < MB * FF && rs + xm < BB)
            xsm[xf * 16 + xm] = x[(size_t)(rs + xm) * T * FF + xf];
    }
    __syncthreads();

    if (tid < 128)
        lstm_body<0>(tid, rs, T, x, We, be, Wd, bd, bog, out, hsm, xsm, wsm, wosm, zex);
    else
        lstm_body<1>(tid, rs, T, x, We, be, Wd, bd, bog, out, hsm, xsm, wsm, wosm, zex);
}

extern "C" void kernel_launch(void* const* d_in, const int* in_sizes, int n_in,
                              void* d_out, int out_size)
{
    const float* x  = (const float*)d_in[0];
    const float* We = (const float*)d_in[1];
    const float* Ue = (const float*)d_in[2];
    const float* be = (const float*)d_in[3];
    const float* Wd = (const float*)d_in[4];
    const float* Ud = (const float*)d_in[5];
    const float* bd = (const float*)d_in[6];
    const float* Wo = (const float*)d_in[7];
    const float* bo = (const float*)d_in[8];
    float* out = (float*)d_out;

    const int T = in_sizes[0] / (BB * FF);
    const int SMEM_BYTES = SM_FLOATS * 4;

    cudaFuncSetAttribute(lstm_ae_kernel,
                         cudaFuncAttributeMaxDynamicSharedMemorySize, SMEM_BYTES);

    transposeU_kernel<<<(H * C4 + 255) / 256, 256>>>(Ue, Ud);
    lstm_ae_kernel<<<(BB + MB - 1) / MB, NT, SMEM_BYTES>>>(x, We, be, Wd, bd, Wo, bo, out, T);
}